// round 5
// baseline (speedup 1.0000x reference)
#include <cuda_runtime.h>

#define NROWS 32768
#define DIM   64
#define KC    1024
#define KT    128
#define THREADS 256
#define NW    (THREADS / 32)
#define NBLOCKS (NROWS / THREADS)   // 128

typedef unsigned long long u64;
typedef unsigned int u32;

// Scratch (device globals: allocation-free)
__device__ u32   g_colmin[KC];
__device__ float g_cnorm[KC];
__device__ float g_mse[NBLOCKS];

// Monotone float <-> uint encoding (atomicMin.u32 == float min, incl. negatives)
__device__ __forceinline__ u32 fenc(float f) {
    u32 u = __float_as_uint(f);
    return u ^ (((u32)((int)u >> 31)) | 0x80000000u);
}
__device__ __forceinline__ float fdec(u32 e) {
    u32 u = (e & 0x80000000u) ? (e ^ 0x80000000u) : ~e;
    return __uint_as_float(u);
}

// ---------------------------------------------------------------------------
// Kernel 0: codebook norms + reset column-min (reset EVERY call: graph replays)
// ---------------------------------------------------------------------------
__global__ void vq_init(const float* __restrict__ cb) {
    int k = blockIdx.x * 128 + threadIdx.x;   // 8 x 128 = 1024
    float s = 0.f;
    const float4* cp = reinterpret_cast<const float4*>(cb + (size_t)k * DIM);
#pragma unroll
    for (int i = 0; i < DIM / 4; i++) {
        float4 c = cp[i];
        s += c.x * c.x + c.y * c.y + c.z * c.z + c.w * c.w;
    }
    g_cnorm[k]  = s;
    g_colmin[k] = 0xFFFFFFFFu;
}

// ---------------------------------------------------------------------------
// Kernel 1: main — argmin per row, column-min per code, MSE partials, output
// ---------------------------------------------------------------------------
__global__ __launch_bounds__(THREADS) void vq_main(
    const float* __restrict__ x,
    const float* __restrict__ cb,
    float* __restrict__ out)
{
    __shared__ alignas(16) float sc[KT * DIM];   // 32 KB codebook tile
    __shared__ float scn[KT];                    // tile norms
    __shared__ u32   swm[NW][KT];                // per-warp column-min (4 KB)
    __shared__ float smse[NW];

    const int row  = blockIdx.x * THREADS + threadIdx.x;
    const int warp = threadIdx.x >> 5;
    const int lane = threadIdx.x & 31;

    // Shared base address (u32) for inline-asm LDS.128
    u32 scb;
    asm("{.reg .u64 t; cvta.to.shared.u64 t, %1; cvt.u32.u64 %0, t;}"
        : "=r"(scb) : "l"(sc));

    // Load this thread's x row; compute ||x||^2; pack to f32x2 operands.
    u64 xv[DIM / 2];
    float xnorm = 0.f;
    {
        const float4* xp = reinterpret_cast<const float4*>(x + (size_t)row * DIM);
#pragma unroll
        for (int i = 0; i < DIM / 4; i++) {
            float4 v = xp[i];
            xnorm += v.x * v.x + v.y * v.y + v.z * v.z + v.w * v.w;
            asm("mov.b64 %0,{%1,%2};" : "=l"(xv[2 * i])     : "f"(v.x), "f"(v.y));
            asm("mov.b64 %0,{%1,%2};" : "=l"(xv[2 * i + 1]) : "f"(v.z), "f"(v.w));
        }
    }

    float best  = 3.4e38f;
    int   bestk = 0;

    for (int kt = 0; kt < KC; kt += KT) {
        __syncthreads();
        // Cooperative tile load: KT*DIM floats = 2048 float4 / 256 threads = 8 each
        {
            const float4* cg = reinterpret_cast<const float4*>(cb + (size_t)kt * DIM);
            float4* s4 = reinterpret_cast<float4*>(sc);
#pragma unroll
            for (int i = 0; i < (KT * DIM / 4) / THREADS; i++)
                s4[threadIdx.x + i * THREADS] = cg[threadIdx.x + i * THREADS];
            if (threadIdx.x < KT) scn[threadIdx.x] = g_cnorm[kt + threadIdx.x];
            // reset per-warp column-min arrays (NW*KT / THREADS = 4 each)
            u32* wm = &swm[0][0];
#pragma unroll
            for (int i = 0; i < (NW * KT) / THREADS; i++)
                wm[threadIdx.x + i * THREADS] = 0xFFFFFFFFu;
        }
        __syncthreads();

#pragma unroll 2
        for (int kk = 0; kk < KT; kk++) {
            const u32 ca = scb + (u32)(kk * (DIM * 4));
            u64 a0 = 0ull, a1 = 0ull, a2 = 0ull, a3 = 0ull;  // (0.f,0.f) packed
            // j indexes u64 elements of the 64-float code row: 32 u64 total.
            // 8 iterations x (2 LDS.128 + 4 FMA2) covers ALL 256 bytes.
#pragma unroll
            for (int j = 0; j < DIM / 2; j += 4) {
                u64 c0, c1, c2, c3;
                asm("ld.shared.v2.u64 {%0,%1},[%2];"
                    : "=l"(c0), "=l"(c1) : "r"(ca + (u32)(j * 8)));
                asm("ld.shared.v2.u64 {%0,%1},[%2];"
                    : "=l"(c2), "=l"(c3) : "r"(ca + (u32)(j * 8 + 16)));
                asm("fma.rn.f32x2 %0,%1,%2,%0;" : "+l"(a0) : "l"(xv[j]),     "l"(c0));
                asm("fma.rn.f32x2 %0,%1,%2,%0;" : "+l"(a1) : "l"(xv[j + 1]), "l"(c1));
                asm("fma.rn.f32x2 %0,%1,%2,%0;" : "+l"(a2) : "l"(xv[j + 2]), "l"(c2));
                asm("fma.rn.f32x2 %0,%1,%2,%0;" : "+l"(a3) : "l"(xv[j + 3]), "l"(c3));
            }
            float l0, h0, l1, h1, l2, h2, l3, h3;
            asm("mov.b64 {%0,%1},%2;" : "=f"(l0), "=f"(h0) : "l"(a0));
            asm("mov.b64 {%0,%1},%2;" : "=f"(l1), "=f"(h1) : "l"(a1));
            asm("mov.b64 {%0,%1},%2;" : "=f"(l2), "=f"(h2) : "l"(a2));
            asm("mov.b64 {%0,%1},%2;" : "=f"(l3), "=f"(h3) : "l"(a3));
            float dot  = ((l0 + h0) + (l1 + h1)) + ((l2 + h2) + (l3 + h3));
            // match reference rounding exactly: (||x||^2 - 2*dot) + ||c||^2
            float dist = (xnorm - 2.f * dot) + scn[kk];
            if (dist < best) { best = dist; bestk = kt + kk; }  // first-index ties
            // warp column-min (single REDUX), lane0 keeps running min in shared
            u32 m = __reduce_min_sync(0xFFFFFFFFu, fenc(dist));
            if (lane == 0) {
                u32 cur = swm[warp][kk];
                if (m < cur) swm[warp][kk] = m;
            }
        }

        // Merge per-warp column-mins -> one global RED per code per block
        __syncthreads();
        if (threadIdx.x < KT) {
            u32 m = swm[0][threadIdx.x];
#pragma unroll
            for (int w = 1; w < NW; w++) {
                u32 v = swm[w][threadIdx.x];
                if (v < m) m = v;
            }
            atomicMin(&g_colmin[kt + threadIdx.x], m);
        }
    }

    // Epilogue: emb = cb[bestk]; out = x + (c - x) (exact reference rounding); MSE
    float mse = 0.f;
    {
        const float2* cbest = reinterpret_cast<const float2*>(cb + (size_t)bestk * DIM);
        float2* op = reinterpret_cast<float2*>(out + (size_t)row * DIM);
#pragma unroll
        for (int i = 0; i < DIM / 2; i++) {
            float xlo, xhi;
            asm("mov.b64 {%0,%1},%2;" : "=f"(xlo), "=f"(xhi) : "l"(xv[i]));
            float2 c = cbest[i];
            float dlo = c.x - xlo;
            float dhi = c.y - xhi;
            mse += dlo * dlo + dhi * dhi;
            float2 o;
            o.x = xlo + dlo;
            o.y = xhi + dhi;
            op[i] = o;
        }
    }
    // Deterministic block reduction of MSE -> per-block partial
#pragma unroll
    for (int o = 16; o > 0; o >>= 1)
        mse += __shfl_down_sync(0xFFFFFFFFu, mse, o);
    if (lane == 0) smse[warp] = mse;
    __syncthreads();
    if (threadIdx.x == 0) {
        float s = 0.f;
#pragma unroll
        for (int i = 0; i < NW; i++) s += smse[i];
        g_mse[blockIdx.x] = s;
    }
}

// ---------------------------------------------------------------------------
// Kernel 2: combine -> loss scalar
// ---------------------------------------------------------------------------
__global__ void vq_final(float* __restrict__ out, int out_size) {
    __shared__ float sw[32];
    int t = threadIdx.x;               // 1024 threads
    float v = fdec(g_colmin[t]);
#pragma unroll
    for (int o = 16; o > 0; o >>= 1)
        v += __shfl_down_sync(0xFFFFFFFFu, v, o);
    if ((t & 31) == 0) sw[t >> 5] = v;
    __syncthreads();
    if (t == 0) {
        float ent = 0.f;
#pragma unroll
        for (int i = 0; i < 32; i++) ent += sw[i];
        float ms = 0.f;
        for (int i = 0; i < NBLOCKS; i++) ms += g_mse[i];
        float m = ms / (float)((size_t)NROWS * DIM);
        // emb_loss(1.0) + commit_loss(0.25) + entropy(0.1), reference add order
        float loss = (m + 0.25f * m) + 0.1f * (ent / (float)KC);
        if (out_size > NROWS * DIM) out[out_size - 1] = loss;
    }
}

// ---------------------------------------------------------------------------
extern "C" void kernel_launch(void* const* d_in, const int* in_sizes, int n_in,
                              void* d_out, int out_size) {
    const float* x  = (const float*)d_in[0];
    const float* cb = (const float*)d_in[1];
    if (n_in >= 2 && in_sizes[0] == KC * DIM && in_sizes[1] == NROWS * DIM) {
        const float* t = x; x = cb; cb = t;
    }
    float* out = (float*)d_out;

    vq_init<<<8, 128>>>(cb);
    vq_main<<<NBLOCKS, THREADS>>>(x, cb, out);
    vq_final<<<1, KC>>>(out, out_size);
}

// round 8
// speedup vs baseline: 1.8632x; 1.8632x over previous
#include <cuda_runtime.h>

#define NROWS   32768
#define DIM     64
#define KC      1024
#define KHALF   512
#define KT      128
#define THREADS 256
#define NW      (THREADS / 32)
#define NRB     (NROWS / THREADS)     // 128 row-blocks
#define NB      (NRB * 2)             // 256 blocks in main

typedef unsigned long long u64;
typedef unsigned int u32;

// Scratch (device globals: allocation-free)
__device__ u64   g_cand[2][NROWS];        // per-half packed (fenc(dist)<<32)|k
__device__ u32   g_colpart[KC * NRB];     // per-(k,rowblock) column-min (encoded)
__device__ float g_mseB[NRB];
__device__ float g_ent;

// Monotone float <-> uint encoding (u32 compare == float compare)
__device__ __forceinline__ u32 fenc(float f) {
    u32 u = __float_as_uint(f);
    return u ^ (((u32)((int)u >> 31)) | 0x80000000u);
}
__device__ __forceinline__ float fdec(u32 e) {
    u32 u = (e & 0x80000000u) ? (e ^ 0x80000000u) : ~e;
    return __uint_as_float(u);
}

// ---------------------------------------------------------------------------
// Kernel A: score 512 codes for 256 rows; per-row candidate + colmin partials
// ---------------------------------------------------------------------------
__global__ __launch_bounds__(THREADS, 2) void vq_main(
    const float* __restrict__ x,
    const float* __restrict__ cb)
{
    __shared__ alignas(16) float sc[KT * DIM];   // 32 KB codebook tile
    __shared__ float scn[KT];                    // tile norms
    __shared__ u32   swm[NW][KT];                // per-warp colmin for tile (4KB)

    const int rowblk = blockIdx.x >> 1;          // adjacent blocks share x rows
    const int khalf  = blockIdx.x & 1;
    const int kbase  = khalf * KHALF;
    const int row    = rowblk * THREADS + threadIdx.x;
    const int warp   = threadIdx.x >> 5;
    const int lane   = threadIdx.x & 31;

    // Register-resident x row + ||x||^2
    float xr[DIM];
    float xnorm = 0.f;
    {
        const float4* xp = reinterpret_cast<const float4*>(x + (size_t)row * DIM);
#pragma unroll
        for (int i = 0; i < DIM / 4; i++) {
            float4 v = xp[i];
            xr[4 * i + 0] = v.x; xr[4 * i + 1] = v.y;
            xr[4 * i + 2] = v.z; xr[4 * i + 3] = v.w;
            xnorm += v.x * v.x + v.y * v.y + v.z * v.z + v.w * v.w;
        }
    }

    float best  = 3.4e38f;
    int   bestk = 0;

    for (int kt = 0; kt < KHALF; kt += KT) {
        __syncthreads();
        // Cooperative tile load: 2048 float4 / 256 threads = 8 each
        {
            const float4* cg =
                reinterpret_cast<const float4*>(cb + (size_t)(kbase + kt) * DIM);
            float4* s4 = reinterpret_cast<float4*>(sc);
#pragma unroll
            for (int i = 0; i < (KT * DIM / 4) / THREADS; i++)
                s4[threadIdx.x + i * THREADS] = cg[threadIdx.x + i * THREADS];
        }
        __syncthreads();
        // Tile norms from smem (threads 0..127, one code each)
        if (threadIdx.x < KT) {
            const float4* cr =
                reinterpret_cast<const float4*>(sc + threadIdx.x * DIM);
            float s = 0.f;
#pragma unroll
            for (int i = 0; i < DIM / 4; i++) {
                float4 c = cr[i];
                s += c.x * c.x + c.y * c.y + c.z * c.z + c.w * c.w;
            }
            scn[threadIdx.x] = s;
        }
        __syncthreads();

        for (int kk = 0; kk < KT; kk++) {
            const float4* c4 = reinterpret_cast<const float4*>(sc) + kk * (DIM / 4);
            float a0 = 0.f, a1 = 0.f, a2 = 0.f, a3 = 0.f;
#pragma unroll
            for (int j = 0; j < DIM / 4; j++) {
                float4 c = c4[j];
                a0 = fmaf(xr[4 * j + 0], c.x, a0);
                a1 = fmaf(xr[4 * j + 1], c.y, a1);
                a2 = fmaf(xr[4 * j + 2], c.z, a2);
                a3 = fmaf(xr[4 * j + 3], c.w, a3);
            }
            float dot  = (a0 + a1) + (a2 + a3);
            // reference rounding: (||x||^2 - 2*dot) + ||c||^2
            float dist = (xnorm - 2.f * dot) + scn[kk];
            if (dist < best) { best = dist; bestk = kt + kk; }   // first-index ties
            u32 m = __reduce_min_sync(0xFFFFFFFFu, fenc(dist));
            if (lane == 0) swm[warp][kk] = m;   // unconditional: flushed per tile
        }

        // Flush per-warp colmins -> global partials (no atomics: unique writer)
        __syncthreads();
        if (threadIdx.x < KT) {
            u32 m = swm[0][threadIdx.x];
#pragma unroll
            for (int w = 1; w < NW; w++) {
                u32 v = swm[w][threadIdx.x];
                if (v < m) m = v;
            }
            g_colpart[(size_t)(kbase + kt + threadIdx.x) * NRB + rowblk] = m;
        }
    }

    // Per-row candidate for this half (thread-private, no reduction)
    g_cand[khalf][row] = ((u64)fenc(best) << 32) | (u32)(kbase + bestk);
}

// ---------------------------------------------------------------------------
// Kernel B: merge halves, write output, MSE partials; block 0 also entropy
// ---------------------------------------------------------------------------
__global__ __launch_bounds__(THREADS) void vq_finish(
    const float* __restrict__ x,
    const float* __restrict__ cb,
    float* __restrict__ out)
{
    __shared__ float smse[NW];
    const int row  = blockIdx.x * THREADS + threadIdx.x;
    const int warp = threadIdx.x >> 5;
    const int lane = threadIdx.x & 31;

    u64 c0 = g_cand[0][row];
    u64 c1 = g_cand[1][row];
    u64 w  = (c1 < c0) ? c1 : c0;    // min dist; ties -> lower k (low bits)
    int k  = (int)(u32)w;

    float mse = 0.f;
    {
        const float4* xp = reinterpret_cast<const float4*>(x + (size_t)row * DIM);
        const float4* cp = reinterpret_cast<const float4*>(cb + (size_t)k * DIM);
        float4* op = reinterpret_cast<float4*>(out + (size_t)row * DIM);
#pragma unroll
        for (int i = 0; i < DIM / 4; i++) {
            float4 xv = xp[i];
            float4 cv = cp[i];
            float dx = cv.x - xv.x, dy = cv.y - xv.y;
            float dz = cv.z - xv.z, dw = cv.w - xv.w;
            mse += dx * dx + dy * dy + dz * dz + dw * dw;
            float4 o;                       // out = x + (c - x), exact ref rounding
            o.x = xv.x + dx; o.y = xv.y + dy;
            o.z = xv.z + dz; o.w = xv.w + dw;
            op[i] = o;
        }
    }
#pragma unroll
    for (int o = 16; o > 0; o >>= 1)
        mse += __shfl_down_sync(0xFFFFFFFFu, mse, o);
    if (lane == 0) smse[warp] = mse;
    __syncthreads();
    if (threadIdx.x == 0) {
        float s = 0.f;
#pragma unroll
        for (int i = 0; i < NW; i++) s += smse[i];
        g_mseB[blockIdx.x] = s;
    }

    // Block 0: entropy = sum over k of min over row-blocks of colpart
    if (blockIdx.x == 0) {
        __shared__ float sent[NW];
        float ps = 0.f;
        for (int k0 = threadIdx.x; k0 < KC; k0 += THREADS) {
            const u32* p = &g_colpart[(size_t)k0 * NRB];
            u32 m = p[0];
            for (int r = 1; r < NRB; r++) {
                u32 v = p[r];
                if (v < m) m = v;
            }
            ps += fdec(m);
        }
#pragma unroll
        for (int o = 16; o > 0; o >>= 1)
            ps += __shfl_down_sync(0xFFFFFFFFu, ps, o);
        if (lane == 0) sent[warp] = ps;
        __syncthreads();
        if (threadIdx.x == 0) {
            float s = 0.f;
#pragma unroll
            for (int i = 0; i < NW; i++) s += sent[i];
            g_ent = s;
        }
    }
}

// ---------------------------------------------------------------------------
// Kernel C: loss scalar
// ---------------------------------------------------------------------------
__global__ void vq_loss(float* __restrict__ out, int out_size) {
    int t = threadIdx.x;   // 32 threads
    float s = 0.f;
    for (int i = t; i < NRB; i += 32) s += g_mseB[i];
#pragma unroll
    for (int o = 16; o > 0; o >>= 1)
        s += __shfl_down_sync(0xFFFFFFFFu, s, o);
    if (t == 0) {
        float m = s / (float)((size_t)NROWS * DIM);
        float loss = (m + 0.25f * m) + 0.1f * (g_ent / (float)KC);
        if (out_size > NROWS * DIM) out[out_size - 1] = loss;
    }
}

// ---------------------------------------------------------------------------
extern "C" void kernel_launch(void* const* d_in, const int* in_sizes, int n_in,
                              void* d_out, int out_size) {
    const float* x  = (const float*)d_in[0];
    const float* cb = (const float*)d_in[1];
    if (n_in >= 2 && in_sizes[0] == KC * DIM && in_sizes[1] == NROWS * DIM) {
        const float* t = x; x = cb; cb = t;
    }
    float* out = (float*)d_out;

    vq_main<<<NB, THREADS>>>(x, cb);
    vq_finish<<<NRB, THREADS>>>(x, cb, out);
    vq_loss<<<1, 32>>>(out, out_size);
}

// round 10
// speedup vs baseline: 2.5334x; 1.3597x over previous
#include <cuda_runtime.h>

#define NROWS   32768
#define DIM     64
#define KC      1024
#define KHALF   512
#define KT      128
#define THREADS 256
#define NW      (THREADS / 32)
#define NRB     (NROWS / THREADS)     // 128 row-blocks
#define NB      (NRB * 2)             // 256 blocks in main
#define ENTB    8

typedef unsigned long long u64;
typedef unsigned int u32;

// Scratch (device globals: allocation-free)
__device__ u64   g_cand[2][NROWS];        // per-half packed (fenc(dist)<<32)|k
__device__ u32   g_colpart[KC * NRB];     // per-(k,rowblock) column-min (encoded)
__device__ float g_mseB[NRB];
__device__ float g_entpart[ENTB];

// Monotone float <-> uint encoding (u32 compare == float compare)
__device__ __forceinline__ u32 fenc(float f) {
    u32 u = __float_as_uint(f);
    return u ^ (((u32)((int)u >> 31)) | 0x80000000u);
}
__device__ __forceinline__ float fdec(u32 e) {
    u32 u = (e & 0x80000000u) ? (e ^ 0x80000000u) : ~e;
    return __uint_as_float(u);
}

// ---------------------------------------------------------------------------
// Kernel A: score 512 codes for 256 rows; per-row candidate + colmin partials
// ---------------------------------------------------------------------------
__global__ __launch_bounds__(THREADS, 2) void vq_main(
    const float* __restrict__ x,
    const float* __restrict__ cb)
{
    __shared__ alignas(16) float sc[KT * DIM];   // 32 KB codebook tile
    __shared__ float scn[KT];                    // tile norms
    __shared__ u32   swm[NW][KT];                // per-warp colmin for tile (4KB)

    const int rowblk = blockIdx.x >> 1;          // adjacent blocks share x rows
    const int khalf  = blockIdx.x & 1;
    const int kbase  = khalf * KHALF;
    const int row    = rowblk * THREADS + threadIdx.x;
    const int warp   = threadIdx.x >> 5;
    const int lane   = threadIdx.x & 31;

    // Register-resident x row packed as f32x2 pairs + ||x||^2
    u64 xv[DIM / 2];
    float xnorm = 0.f;
    {
        const float4* xp = reinterpret_cast<const float4*>(x + (size_t)row * DIM);
#pragma unroll
        for (int i = 0; i < DIM / 4; i++) {
            float4 v = xp[i];
            xnorm += v.x * v.x + v.y * v.y + v.z * v.z + v.w * v.w;
            asm("mov.b64 %0,{%1,%2};" : "=l"(xv[2 * i])     : "f"(v.x), "f"(v.y));
            asm("mov.b64 %0,{%1,%2};" : "=l"(xv[2 * i + 1]) : "f"(v.z), "f"(v.w));
        }
    }

    float best  = 3.4e38f;
    int   bestk = 0;

    for (int kt = 0; kt < KHALF; kt += KT) {
        __syncthreads();
        // Cooperative tile load: 2048 float4 / 256 threads = 8 each
        {
            const float4* cg =
                reinterpret_cast<const float4*>(cb + (size_t)(kbase + kt) * DIM);
            float4* s4 = reinterpret_cast<float4*>(sc);
#pragma unroll
            for (int i = 0; i < (KT * DIM / 4) / THREADS; i++)
                s4[threadIdx.x + i * THREADS] = cg[threadIdx.x + i * THREADS];
        }
        __syncthreads();
        // Tile norms from smem (threads 0..127, one code each)
        if (threadIdx.x < KT) {
            const float4* cr =
                reinterpret_cast<const float4*>(sc + threadIdx.x * DIM);
            float s = 0.f;
#pragma unroll
            for (int i = 0; i < DIM / 4; i++) {
                float4 c = cr[i];
                s += c.x * c.x + c.y * c.y + c.z * c.z + c.w * c.w;
            }
            scn[threadIdx.x] = s;
        }
        __syncthreads();

        for (int kk = 0; kk < KT; kk++) {
            const ulonglong2* c2 =
                reinterpret_cast<const ulonglong2*>(sc + kk * DIM);
            u64 a0 = 0ull, a1 = 0ull, a2 = 0ull, a3 = 0ull;  // (0.f,0.f) packed
#pragma unroll
            for (int j = 0; j < DIM / 4; j += 2) {            // 8 iters
                ulonglong2 p = c2[j];
                ulonglong2 q = c2[j + 1];
                asm("fma.rn.f32x2 %0,%1,%2,%0;" : "+l"(a0) : "l"(xv[2*j]),   "l"(p.x));
                asm("fma.rn.f32x2 %0,%1,%2,%0;" : "+l"(a1) : "l"(xv[2*j+1]), "l"(p.y));
                asm("fma.rn.f32x2 %0,%1,%2,%0;" : "+l"(a2) : "l"(xv[2*j+2]), "l"(q.x));
                asm("fma.rn.f32x2 %0,%1,%2,%0;" : "+l"(a3) : "l"(xv[2*j+3]), "l"(q.y));
            }
            float l0, h0, l1, h1, l2, h2, l3, h3;
            asm("mov.b64 {%0,%1},%2;" : "=f"(l0), "=f"(h0) : "l"(a0));
            asm("mov.b64 {%0,%1},%2;" : "=f"(l1), "=f"(h1) : "l"(a1));
            asm("mov.b64 {%0,%1},%2;" : "=f"(l2), "=f"(h2) : "l"(a2));
            asm("mov.b64 {%0,%1},%2;" : "=f"(l3), "=f"(h3) : "l"(a3));
            float dot  = ((l0 + h0) + (l1 + h1)) + ((l2 + h2) + (l3 + h3));
            // reference rounding: (||x||^2 - 2*dot) + ||c||^2
            float dist = (xnorm - 2.f * dot) + scn[kk];
            if (dist < best) { best = dist; bestk = kt + kk; }   // first-index ties
            u32 m = __reduce_min_sync(0xFFFFFFFFu, fenc(dist));
            if (lane == 0) swm[warp][kk] = m;   // unconditional: flushed per tile
        }

        // Flush per-warp colmins -> global partials (no atomics: unique writer)
        __syncthreads();
        if (threadIdx.x < KT) {
            u32 m = swm[0][threadIdx.x];
#pragma unroll
            for (int w = 1; w < NW; w++) {
                u32 v = swm[w][threadIdx.x];
                if (v < m) m = v;
            }
            g_colpart[(size_t)(kbase + kt + threadIdx.x) * NRB + rowblk] = m;
        }
    }

    // Per-row candidate for this half (thread-private, no reduction)
    g_cand[khalf][row] = ((u64)fenc(best) << 32) | (u32)(kbase + bestk);
}

// ---------------------------------------------------------------------------
// Kernel B: parallel entropy reduction (was serialized in one block before)
// ---------------------------------------------------------------------------
__global__ __launch_bounds__(128) void vq_ent() {
    __shared__ float sent[4];
    const int k    = blockIdx.x * 128 + threadIdx.x;   // 8 x 128 = 1024
    const int warp = threadIdx.x >> 5;
    const int lane = threadIdx.x & 31;

    const u32* p = &g_colpart[(size_t)k * NRB];
    u32 m = 0xFFFFFFFFu;
#pragma unroll 8
    for (int r = 0; r < NRB; r++) {
        u32 v = p[r];
        if (v < m) m = v;
    }
    float s = fdec(m);
#pragma unroll
    for (int o = 16; o > 0; o >>= 1)
        s += __shfl_down_sync(0xFFFFFFFFu, s, o);
    if (lane == 0) sent[warp] = s;
    __syncthreads();
    if (threadIdx.x == 0)
        g_entpart[blockIdx.x] = (sent[0] + sent[1]) + (sent[2] + sent[3]);
}

// ---------------------------------------------------------------------------
// Kernel C: merge halves, write output, MSE partials
// ---------------------------------------------------------------------------
__global__ __launch_bounds__(THREADS) void vq_finish(
    const float* __restrict__ x,
    const float* __restrict__ cb,
    float* __restrict__ out)
{
    __shared__ float smse[NW];
    const int row  = blockIdx.x * THREADS + threadIdx.x;
    const int warp = threadIdx.x >> 5;
    const int lane = threadIdx.x & 31;

    u64 c0 = g_cand[0][row];
    u64 c1 = g_cand[1][row];
    u64 w  = (c1 < c0) ? c1 : c0;    // min dist; ties -> lower k (low bits)
    int k  = (int)(u32)w;

    float mse = 0.f;
    {
        const float4* xp = reinterpret_cast<const float4*>(x + (size_t)row * DIM);
        const float4* cp = reinterpret_cast<const float4*>(cb + (size_t)k * DIM);
        float4* op = reinterpret_cast<float4*>(out + (size_t)row * DIM);
#pragma unroll
        for (int i = 0; i < DIM / 4; i++) {
            float4 xv = xp[i];
            float4 cv = cp[i];
            float dx = cv.x - xv.x, dy = cv.y - xv.y;
            float dz = cv.z - xv.z, dw = cv.w - xv.w;
            mse += dx * dx + dy * dy + dz * dz + dw * dw;
            float4 o;                       // out = x + (c - x), exact ref rounding
            o.x = xv.x + dx; o.y = xv.y + dy;
            o.z = xv.z + dz; o.w = xv.w + dw;
            op[i] = o;
        }
    }
#pragma unroll
    for (int o = 16; o > 0; o >>= 1)
        mse += __shfl_down_sync(0xFFFFFFFFu, mse, o);
    if (lane == 0) smse[warp] = mse;
    __syncthreads();
    if (threadIdx.x == 0) {
        float s = 0.f;
#pragma unroll
        for (int i = 0; i < NW; i++) s += smse[i];
        g_mseB[blockIdx.x] = s;
    }
}

// ---------------------------------------------------------------------------
// Kernel D: loss scalar
// ---------------------------------------------------------------------------
__global__ void vq_loss(float* __restrict__ out, int out_size) {
    int t = threadIdx.x;   // 32 threads
    float s = 0.f;
    for (int i = t; i < NRB; i += 32) s += g_mseB[i];
#pragma unroll
    for (int o = 16; o > 0; o >>= 1)
        s += __shfl_down_sync(0xFFFFFFFFu, s, o);
    if (t == 0) {
        float ent = 0.f;
#pragma unroll
        for (int i = 0; i < ENTB; i++) ent += g_entpart[i];
        float m = s / (float)((size_t)NROWS * DIM);
        float loss = (m + 0.25f * m) + 0.1f * (ent / (float)KC);
        if (out_size > NROWS * DIM) out[out_size - 1] = loss;
    }
}

// ---------------------------------------------------------------------------
extern "C" void kernel_launch(void* const* d_in, const int* in_sizes, int n_in,
                              void* d_out, int out_size) {
    const float* x  = (const float*)d_in[0];
    const float* cb = (const float*)d_in[1];
    if (n_in >= 2 && in_sizes[0] == KC * DIM && in_sizes[1] == NROWS * DIM) {
        const float* t = x; x = cb; cb = t;
    }
    float* out = (float*)d_out;

    vq_main<<<NB, THREADS>>>(x, cb);
    vq_ent<<<ENTB, 128>>>();
    vq_finish<<<NRB, THREADS>>>(x, cb, out);
    vq_loss<<<1, 32>>>(out, out_size);
}

// round 12
// speedup vs baseline: 2.6544x; 1.0478x over previous
#include <cuda_runtime.h>

#define NROWS   32768
#define DIM     64
#define KC      1024
#define KHALF   512
#define KT      128
#define THREADS 256
#define NW      (THREADS / 32)
#define NRB     (NROWS / THREADS)     // 128 row-blocks
#define NB      (NRB * 2)             // 256 blocks in main
#define ENTB    8

typedef unsigned long long u64;
typedef unsigned int u32;

// Scratch (device globals: allocation-free; zero-init at load)
__device__ u64   g_cand[2][NROWS];        // per-half packed (fenc(dist)<<32)|k
__device__ u32   g_colpart[NRB * KC];     // [rowblk][k] column-min partials
__device__ float g_mseB[NRB];
__device__ float g_entpart[ENTB];
__device__ u32   g_entdone;               // self-resetting completion counter

// Monotone float <-> uint encoding (u32 compare == float compare)
__device__ __forceinline__ u32 fenc(float f) {
    u32 u = __float_as_uint(f);
    return u ^ (((u32)((int)u >> 31)) | 0x80000000u);
}
__device__ __forceinline__ float fdec(u32 e) {
    u32 u = (e & 0x80000000u) ? (e ^ 0x80000000u) : ~e;
    return __uint_as_float(u);
}

// ---------------------------------------------------------------------------
// Kernel A: score 512 codes for 256 rows; per-row candidate + colmin partials
// ---------------------------------------------------------------------------
__global__ __launch_bounds__(THREADS, 2) void vq_main(
    const float* __restrict__ x,
    const float* __restrict__ cb)
{
    __shared__ alignas(16) float sc[KT * DIM];   // 32 KB codebook tile
    __shared__ float scn[KT];                    // tile norms
    __shared__ u32   swm[NW][KT];                // per-warp colmin for tile (4KB)

    const int rowblk = blockIdx.x >> 1;          // adjacent blocks share x rows
    const int khalf  = blockIdx.x & 1;
    const int kbase  = khalf * KHALF;
    const int row    = rowblk * THREADS + threadIdx.x;
    const int warp   = threadIdx.x >> 5;
    const int lane   = threadIdx.x & 31;

    // Register-resident x row packed as f32x2 pairs + ||x||^2
    u64 xv[DIM / 2];
    float xnorm = 0.f;
    {
        const float4* xp = reinterpret_cast<const float4*>(x + (size_t)row * DIM);
#pragma unroll
        for (int i = 0; i < DIM / 4; i++) {
            float4 v = xp[i];
            xnorm += v.x * v.x + v.y * v.y + v.z * v.z + v.w * v.w;
            asm("mov.b64 %0,{%1,%2};" : "=l"(xv[2 * i])     : "f"(v.x), "f"(v.y));
            asm("mov.b64 %0,{%1,%2};" : "=l"(xv[2 * i + 1]) : "f"(v.z), "f"(v.w));
        }
    }

    float best  = 3.4e38f;
    int   bestk = 0;

    for (int kt = 0; kt < KHALF; kt += KT) {
        __syncthreads();
        // Cooperative tile load: 2048 float4 / 256 threads = 8 each
        {
            const float4* cg =
                reinterpret_cast<const float4*>(cb + (size_t)(kbase + kt) * DIM);
            float4* s4 = reinterpret_cast<float4*>(sc);
#pragma unroll
            for (int i = 0; i < (KT * DIM / 4) / THREADS; i++)
                s4[threadIdx.x + i * THREADS] = cg[threadIdx.x + i * THREADS];
        }
        __syncthreads();
        // Tile norms from smem (threads 0..127, one code each)
        if (threadIdx.x < KT) {
            const float4* cr =
                reinterpret_cast<const float4*>(sc + threadIdx.x * DIM);
            float s = 0.f;
#pragma unroll
            for (int i = 0; i < DIM / 4; i++) {
                float4 c = cr[i];
                s += c.x * c.x + c.y * c.y + c.z * c.z + c.w * c.w;
            }
            scn[threadIdx.x] = s;
        }
        __syncthreads();

        // 2 codes per iteration: overlapped tails, fewer per-code issues
        for (int kk = 0; kk < KT; kk += 2) {
            const ulonglong2* cc =
                reinterpret_cast<const ulonglong2*>(sc + kk * DIM);  // [0..15]=code0, [16..31]=code1
            u64 a0 = 0ull, a1 = 0ull;   // code0 accumulators (f32x2)
            u64 b0 = 0ull, b1 = 0ull;   // code1 accumulators
#pragma unroll
            for (int j = 0; j < 16; j += 2) {
                ulonglong2 p0 = cc[j];
                ulonglong2 p1 = cc[j + 1];
                ulonglong2 q0 = cc[16 + j];
                ulonglong2 q1 = cc[17 + j];
                asm("fma.rn.f32x2 %0,%1,%2,%0;" : "+l"(a0) : "l"(xv[2*j]),   "l"(p0.x));
                asm("fma.rn.f32x2 %0,%1,%2,%0;" : "+l"(a1) : "l"(xv[2*j+1]), "l"(p0.y));
                asm("fma.rn.f32x2 %0,%1,%2,%0;" : "+l"(b0) : "l"(xv[2*j]),   "l"(q0.x));
                asm("fma.rn.f32x2 %0,%1,%2,%0;" : "+l"(b1) : "l"(xv[2*j+1]), "l"(q0.y));
                asm("fma.rn.f32x2 %0,%1,%2,%0;" : "+l"(a0) : "l"(xv[2*j+2]), "l"(p1.x));
                asm("fma.rn.f32x2 %0,%1,%2,%0;" : "+l"(a1) : "l"(xv[2*j+3]), "l"(p1.y));
                asm("fma.rn.f32x2 %0,%1,%2,%0;" : "+l"(b0) : "l"(xv[2*j+2]), "l"(q1.x));
                asm("fma.rn.f32x2 %0,%1,%2,%0;" : "+l"(b1) : "l"(xv[2*j+3]), "l"(q1.y));
            }
            // Packed reduction tree: 1 packed add + unpack + 1 scalar add per code
            u64 sa, sb;
            asm("add.rn.f32x2 %0,%1,%2;" : "=l"(sa) : "l"(a0), "l"(a1));
            asm("add.rn.f32x2 %0,%1,%2;" : "=l"(sb) : "l"(b0), "l"(b1));
            float al, ah, bl, bh;
            asm("mov.b64 {%0,%1},%2;" : "=f"(al), "=f"(ah) : "l"(sa));
            asm("mov.b64 {%0,%1},%2;" : "=f"(bl), "=f"(bh) : "l"(sb));
            float dot0 = al + ah;
            float dot1 = bl + bh;
            float dist0 = (xnorm - 2.f * dot0) + scn[kk];
            float dist1 = (xnorm - 2.f * dot1) + scn[kk + 1];
            if (dist0 < best) { best = dist0; bestk = kt + kk; }       // first-index
            if (dist1 < best) { best = dist1; bestk = kt + kk + 1; }   // ties kept
            u32 m0 = __reduce_min_sync(0xFFFFFFFFu, fenc(dist0));
            u32 m1 = __reduce_min_sync(0xFFFFFFFFu, fenc(dist1));
            if (lane == 0) {
                swm[warp][kk]     = m0;
                swm[warp][kk + 1] = m1;
            }
        }

        // Flush per-warp colmins -> global partials (coalesced, unique writer)
        __syncthreads();
        if (threadIdx.x < KT) {
            u32 m = swm[0][threadIdx.x];
#pragma unroll
            for (int w = 1; w < NW; w++) {
                u32 v = swm[w][threadIdx.x];
                if (v < m) m = v;
            }
            g_colpart[(size_t)rowblk * KC + (kbase + kt + threadIdx.x)] = m;
        }
    }

    // Per-row candidate for this half (thread-private, no reduction)
    g_cand[khalf][row] = ((u64)fenc(best) << 32) | (u32)(kbase + bestk);
}

// ---------------------------------------------------------------------------
// Kernel B: merge halves, write output, MSE partials
// ---------------------------------------------------------------------------
__global__ __launch_bounds__(THREADS) void vq_finish(
    const float* __restrict__ x,
    const float* __restrict__ cb,
    float* __restrict__ out)
{
    __shared__ float smse[NW];
    const int row  = blockIdx.x * THREADS + threadIdx.x;
    const int warp = threadIdx.x >> 5;
    const int lane = threadIdx.x & 31;

    u64 c0 = g_cand[0][row];
    u64 c1 = g_cand[1][row];
    u64 w  = (c1 < c0) ? c1 : c0;    // min dist; ties -> lower k (low bits)
    int k  = (int)(u32)w;

    float mse = 0.f;
    {
        const float4* xp = reinterpret_cast<const float4*>(x + (size_t)row * DIM);
        const float4* cp = reinterpret_cast<const float4*>(cb + (size_t)k * DIM);
        float4* op = reinterpret_cast<float4*>(out + (size_t)row * DIM);
#pragma unroll
        for (int i = 0; i < DIM / 4; i++) {
            float4 xv = xp[i];
            float4 cv = cp[i];
            float dx = cv.x - xv.x, dy = cv.y - xv.y;
            float dz = cv.z - xv.z, dw = cv.w - xv.w;
            mse += dx * dx + dy * dy + dz * dz + dw * dw;
            float4 o;                       // out = x + (c - x), exact ref rounding
            o.x = xv.x + dx; o.y = xv.y + dy;
            o.z = xv.z + dz; o.w = xv.w + dw;
            op[i] = o;
        }
    }
#pragma unroll
    for (int o = 16; o > 0; o >>= 1)
        mse += __shfl_down_sync(0xFFFFFFFFu, mse, o);
    if (lane == 0) smse[warp] = mse;
    __syncthreads();
    if (threadIdx.x == 0) {
        float s = 0.f;
#pragma unroll
        for (int i = 0; i < NW; i++) s += smse[i];
        g_mseB[blockIdx.x] = s;
    }
}

// ---------------------------------------------------------------------------
// Kernel C: entropy reduction + (last block) loss scalar — fused
// ---------------------------------------------------------------------------
__global__ __launch_bounds__(128) void vq_entloss(float* __restrict__ out,
                                                  int out_size) {
    __shared__ float sent[4];
    __shared__ u32 slast;
    const int k    = blockIdx.x * 128 + threadIdx.x;   // 8 x 128 = 1024
    const int warp = threadIdx.x >> 5;
    const int lane = threadIdx.x & 31;

    // min over row-blocks; coalesced: warp reads 128 consecutive u32 per r
    u32 m = 0xFFFFFFFFu;
#pragma unroll 8
    for (int r = 0; r < NRB; r++) {
        u32 v = g_colpart[(size_t)r * KC + k];
        if (v < m) m = v;
    }
    float s = fdec(m);
#pragma unroll
    for (int o = 16; o > 0; o >>= 1)
        s += __shfl_down_sync(0xFFFFFFFFu, s, o);
    if (lane == 0) sent[warp] = s;
    __syncthreads();
    if (threadIdx.x == 0) {
        g_entpart[blockIdx.x] = (sent[0] + sent[1]) + (sent[2] + sent[3]);
        __threadfence();
        slast = (atomicAdd(&g_entdone, 1u) == ENTB - 1);
    }
    __syncthreads();

    // Last block to finish: final loss (deterministic sum order) + counter reset
    if (slast && warp == 0) {
        float ms = 0.f;
        for (int i = lane; i < NRB; i += 32) ms += g_mseB[i];
#pragma unroll
        for (int o = 16; o > 0; o >>= 1)
            ms += __shfl_down_sync(0xFFFFFFFFu, ms, o);
        if (lane == 0) {
            float ent = 0.f;
#pragma unroll
            for (int i = 0; i < ENTB; i++) ent += g_entpart[i];
            float mm = ms / (float)((size_t)NROWS * DIM);
            float loss = (mm + 0.25f * mm) + 0.1f * (ent / (float)KC);
            if (out_size > NROWS * DIM) out[out_size - 1] = loss;
            g_entdone = 0;   // self-reset for next graph replay
        }
    }
}

// ---------------------------------------------------------------------------
extern "C" void kernel_launch(void* const* d_in, const int* in_sizes, int n_in,
                              void* d_out, int out_size) {
    const float* x  = (const float*)d_in[0];
    const float* cb = (const float*)d_in[1];
    if (n_in >= 2 && in_sizes[0] == KC * DIM && in_sizes[1] == NROWS * DIM) {
        const float* t = x; x = cb; cb = t;
    }
    float* out = (float*)d_out;

    vq_main<<<NB, THREADS>>>(x, cb);
    vq_finish<<<NRB, THREADS>>>(x, cb, out);
    vq_entloss<<<ENTB, 128>>>(out, out_size);
}